// round 1
// baseline (speedup 1.0000x reference)
#include <cuda_runtime.h>
#include <math.h>

#define N_Q   8192
#define M_KV  8192
#define DIM   256
#define KNB   32
#define TAU_F 0.07f
#define EPS_F 1e-8f

#define BM 128
#define BN 128
#define BK 16
#define SST 132   // smem row stride in floats (528B: 16B aligned, depolarizes banks)

// scratch (device globals: allocation-free per harness rules)
__device__ float g_F[16384 * 256];                 // 16 MB  features pre-norm
__device__ float g_fxn[8192 * 256];                // 8 MB   normalized x-features, row-major
__device__ float g_fynT[256 * 8192];               // 8 MB   normalized y-features, TRANSPOSED [D][M]
__device__ float g_sim[(size_t)8192 * 8192];       // 256 MB similarity matrix

typedef unsigned long long u64;

__device__ __forceinline__ u64 pk2(float lo, float hi) {
    u64 r; asm("mov.b64 %0, {%1, %2};" : "=l"(r) : "f"(lo), "f"(hi)); return r;
}
__device__ __forceinline__ void unpk2(u64 p, float& lo, float& hi) {
    asm("mov.b64 {%0, %1}, %2;" : "=f"(lo), "=f"(hi) : "l"(p));
}
// packed fp32x2 FMA: 2 FMA lanes per instruction (ptxas never auto-fuses this)
__device__ __forceinline__ void ffma2(u64& d, u64 a, u64 b) {
    asm("fma.rn.f32x2 %0, %1, %2, %0;" : "+l"(d) : "l"(a), "l"(b));
}

// ---------------------------------------------------------------------------
// Kernel 1: F = [x;y] @ W^T + b   (M=16384, N=256, K=256), fp32 via f32x2
// ---------------------------------------------------------------------------
__global__ __launch_bounds__(256, 2)
void feat_gemm_kernel(const float* __restrict__ x, const float* __restrict__ y,
                      const float* __restrict__ W, const float* __restrict__ bias)
{
    __shared__ float As[BK * SST];
    __shared__ float Bs[BK * SST];
    const int tid = threadIdx.x;
    const int tr  = tid >> 4;          // 0..15, 8 rows each
    const int tc  = tid & 15;          // 0..15, 8 cols each
    const int r0  = blockIdx.y * BM;
    const int c0  = blockIdx.x * BN;

    u64 acc[8][4];
#pragma unroll
    for (int i = 0; i < 8; i++)
#pragma unroll
        for (int j = 0; j < 4; j++) acc[i][j] = 0ull;

    for (int k0 = 0; k0 < DIM; k0 += BK) {
        // A tile: Z[r0..+128][k0..+16]  -> As[k][r] (transposed)
#pragma unroll
        for (int ld = 0; ld < 2; ld++) {
            int pos = tid + ld * 256;          // 0..511
            int r   = pos >> 2;                // 0..127
            int kg  = pos & 3;                 // float4 group in k
            int gr  = r0 + r;
            const float* src = (gr < N_Q) ? (x + (size_t)gr * DIM)
                                          : (y + (size_t)(gr - N_Q) * DIM);
            float4 v = *(const float4*)(src + k0 + kg * 4);
            As[(kg * 4 + 0) * SST + r] = v.x;
            As[(kg * 4 + 1) * SST + r] = v.y;
            As[(kg * 4 + 2) * SST + r] = v.z;
            As[(kg * 4 + 3) * SST + r] = v.w;
        }
        // B tile: Bs[k][c] = W[c0+c][k0+k]  (W row-major [D][D])
#pragma unroll
        for (int ld = 0; ld < 2; ld++) {
            int pos = tid + ld * 256;
            int c   = pos >> 2;                // 0..127
            int kg  = pos & 3;
            float4 v = *(const float4*)(W + (size_t)(c0 + c) * DIM + k0 + kg * 4);
            Bs[(kg * 4 + 0) * SST + c] = v.x;
            Bs[(kg * 4 + 1) * SST + c] = v.y;
            Bs[(kg * 4 + 2) * SST + c] = v.z;
            Bs[(kg * 4 + 3) * SST + c] = v.w;
        }
        __syncthreads();
#pragma unroll
        for (int kk = 0; kk < BK; kk++) {
            const float* ar = As + kk * SST + tr * 8;
            const u64*   br = (const u64*)(Bs + kk * SST + tc * 8);
            float4 a0 = *(const float4*)(ar);
            float4 a1 = *(const float4*)(ar + 4);
            u64 b0 = br[0], b1 = br[1], b2 = br[2], b3 = br[3];
            float av[8] = {a0.x, a0.y, a0.z, a0.w, a1.x, a1.y, a1.z, a1.w};
#pragma unroll
            for (int i = 0; i < 8; i++) {
                u64 ai = pk2(av[i], av[i]);
                ffma2(acc[i][0], ai, b0);
                ffma2(acc[i][1], ai, b1);
                ffma2(acc[i][2], ai, b2);
                ffma2(acc[i][3], ai, b3);
            }
        }
        __syncthreads();
    }

    float bl[8];
#pragma unroll
    for (int u = 0; u < 8; u++) bl[u] = bias[c0 + tc * 8 + u];
#pragma unroll
    for (int i = 0; i < 8; i++) {
        int row = r0 + tr * 8 + i;
        float* dst = g_F + (size_t)row * DIM + c0 + tc * 8;
        float4 w0, w1;
        unpk2(acc[i][0], w0.x, w0.y); unpk2(acc[i][1], w0.z, w0.w);
        unpk2(acc[i][2], w1.x, w1.y); unpk2(acc[i][3], w1.z, w1.w);
        w0.x += bl[0]; w0.y += bl[1]; w0.z += bl[2]; w0.w += bl[3];
        w1.x += bl[4]; w1.y += bl[5]; w1.z += bl[6]; w1.w += bl[7];
        *(float4*)dst       = w0;
        *(float4*)(dst + 4) = w1;
    }
}

// ---------------------------------------------------------------------------
// Kernel 2: L2-normalize each row of F. x-rows -> g_fxn (row major),
//           y-rows -> g_fynT (transposed [D][M] for coalesced GEMM B loads)
// ---------------------------------------------------------------------------
__global__ __launch_bounds__(256)
void normalize_kernel()
{
    const int row = blockIdx.x;
    const int t   = threadIdx.x;          // 0..255 == feature index
    float v = g_F[(size_t)row * DIM + t];
    float sq = v * v;
#pragma unroll
    for (int o = 16; o > 0; o >>= 1) sq += __shfl_xor_sync(0xffffffffu, sq, o);
    __shared__ float ws[8];
    __shared__ float sres;
    if ((t & 31) == 0) ws[t >> 5] = sq;
    __syncthreads();
    if (t < 32) {
        float total = (t < 8) ? ws[t] : 0.0f;
#pragma unroll
        for (int o = 4; o > 0; o >>= 1) total += __shfl_xor_sync(0xffffffffu, total, o);
        if (t == 0) sres = rsqrtf(total + EPS_F);
    }
    __syncthreads();
    float s = sres;
    float o = v * s;
    if (row < N_Q) g_fxn[(size_t)row * DIM + t] = o;
    else           g_fynT[(size_t)t * M_KV + (row - N_Q)] = o;
}

// ---------------------------------------------------------------------------
// Kernel 3: sim = fxn @ fynT   (8192 x 8192 x 256), fp32 via f32x2
// ---------------------------------------------------------------------------
__global__ __launch_bounds__(256, 2)
void sim_gemm_kernel()
{
    __shared__ float As[BK * SST];
    __shared__ float Bs[BK * SST];
    const int tid = threadIdx.x;
    const int tr  = tid >> 4;
    const int tc  = tid & 15;
    const int r0  = blockIdx.y * BM;
    const int c0  = blockIdx.x * BN;

    u64 acc[8][4];
#pragma unroll
    for (int i = 0; i < 8; i++)
#pragma unroll
        for (int j = 0; j < 4; j++) acc[i][j] = 0ull;

    for (int k0 = 0; k0 < DIM; k0 += BK) {
        // A tile (g_fxn, row-major) -> As[k][r]
#pragma unroll
        for (int ld = 0; ld < 2; ld++) {
            int pos = tid + ld * 256;
            int r   = pos >> 2;
            int kg  = pos & 3;
            float4 v = *(const float4*)(g_fxn + (size_t)(r0 + r) * DIM + k0 + kg * 4);
            As[(kg * 4 + 0) * SST + r] = v.x;
            As[(kg * 4 + 1) * SST + r] = v.y;
            As[(kg * 4 + 2) * SST + r] = v.z;
            As[(kg * 4 + 3) * SST + r] = v.w;
        }
        // B tile (g_fynT, [D][M] row-major: k-rows contiguous in cols) -> Bs[k][c]
#pragma unroll
        for (int ld = 0; ld < 2; ld++) {
            int pos = tid + ld * 256;
            int k   = pos >> 5;                // 0..15
            int cg  = pos & 31;                // 32 float4 groups cover 128 cols
            float4 v = *(const float4*)(g_fynT + (size_t)(k0 + k) * M_KV + c0 + cg * 4);
            *(float4*)(Bs + k * SST + cg * 4) = v;
        }
        __syncthreads();
#pragma unroll
        for (int kk = 0; kk < BK; kk++) {
            const float* ar = As + kk * SST + tr * 8;
            const u64*   br = (const u64*)(Bs + kk * SST + tc * 8);
            float4 a0 = *(const float4*)(ar);
            float4 a1 = *(const float4*)(ar + 4);
            u64 b0 = br[0], b1 = br[1], b2 = br[2], b3 = br[3];
            float av[8] = {a0.x, a0.y, a0.z, a0.w, a1.x, a1.y, a1.z, a1.w};
#pragma unroll
            for (int i = 0; i < 8; i++) {
                u64 ai = pk2(av[i], av[i]);
                ffma2(acc[i][0], ai, b0);
                ffma2(acc[i][1], ai, b1);
                ffma2(acc[i][2], ai, b2);
                ffma2(acc[i][3], ai, b3);
            }
        }
        __syncthreads();
    }
#pragma unroll
    for (int i = 0; i < 8; i++) {
        int row = r0 + tr * 8 + i;
        float* dst = g_sim + (size_t)row * M_KV + c0 + tc * 8;
        float4 w0, w1;
        unpk2(acc[i][0], w0.x, w0.y); unpk2(acc[i][1], w0.z, w0.w);
        unpk2(acc[i][2], w1.x, w1.y); unpk2(acc[i][3], w1.z, w1.w);
        *(float4*)dst       = w0;
        *(float4*)(dst + 4) = w1;
    }
}

// ---------------------------------------------------------------------------
// Kernel 4: exact top-32 per row (jax tie-break: equal values -> lower index
// first), temperature softmax over the 32, write soft + idx.
// One warp per row; threshold-pruned streaming (expected ~210 insertions/row).
// ---------------------------------------------------------------------------
__global__ __launch_bounds__(256)
void topk_kernel(float* __restrict__ out, int out_size)
{
    const unsigned FULL = 0xffffffffu;
    const int gw   = (blockIdx.x * blockDim.x + threadIdx.x) >> 5;  // row
    const int lane = threadIdx.x & 31;
    if (gw >= N_Q) return;
    const float* row = g_sim + (size_t)gw * M_KV;

    float v  = -3.0e38f;   // my slot value (one of the current top-32)
    int   ii = -1;         // my slot column index
    float mn = -3.0e38f;   // warp-uniform min of the 32 slots

    for (int base = 0; base < M_KV; base += 128) {
        float4 nv = *(const float4*)(row + base + lane * 4);
        float cand[4] = {nv.x, nv.y, nv.z, nv.w};
#pragma unroll
        for (int q = 0; q < 4; q++) {
            unsigned bal = __ballot_sync(FULL, cand[q] > mn);
            while (bal) {
                int src = __ffs(bal) - 1;
                bal &= bal - 1;
                float cv = __shfl_sync(FULL, cand[q], src);
                int   ci = base + src * 4 + q;
                if (cv > mn) {   // re-check against updated threshold (strict >: keeps earlier index on ties)
                    // warp argmin over slots
                    float m = v; int ml = lane;
#pragma unroll
                    for (int o = 16; o > 0; o >>= 1) {
                        float om  = __shfl_xor_sync(FULL, m, o);
                        int   oml = __shfl_xor_sync(FULL, ml, o);
                        if (om < m || (om == m && oml < ml)) { m = om; ml = oml; }
                    }
                    if (lane == ml) { v = cv; ii = ci; }
                    float t = v;
#pragma unroll
                    for (int o = 16; o > 0; o >>= 1) t = fminf(t, __shfl_xor_sync(FULL, t, o));
                    mn = t;
                }
            }
        }
    }

    // bitonic sort (descending by value, ascending by index on ties)
#pragma unroll
    for (int k = 2; k <= 32; k <<= 1) {
#pragma unroll
        for (int j = k >> 1; j > 0; j >>= 1) {
            float ov = __shfl_xor_sync(FULL, v, j);
            int   oi = __shfl_xor_sync(FULL, ii, j);
            bool up    = ((lane & k) == 0);
            bool lower = ((lane & j) == 0);
            bool otherWins = (ov > v) || (ov == v && oi < ii);
            bool take = (lower == up) ? otherWins : !otherWins;
            if (take) { v = ov; ii = oi; }
        }
    }

    // softmax over the 32 values (temperature TAU)
    float top = __shfl_sync(FULL, v, 0);
    float e = expf((v - top) / TAU_F);
    float s = e;
#pragma unroll
    for (int o = 16; o > 0; o >>= 1) s += __shfl_xor_sync(FULL, s, o);
    float soft = e / s;

    out[(size_t)gw * KNB + lane] = soft;
    if (out_size >= 2 * N_Q * KNB)
        out[(size_t)N_Q * KNB + (size_t)gw * KNB + lane] = (float)ii;
}

// ---------------------------------------------------------------------------
extern "C" void kernel_launch(void* const* d_in, const int* in_sizes, int n_in,
                              void* d_out, int out_size)
{
    const float* x = (const float*)d_in[0];
    const float* y = (const float*)d_in[1];
    const float* W = (const float*)d_in[2];
    const float* b = (const float*)d_in[3];
    float* out = (float*)d_out;
    (void)in_sizes; (void)n_in;

    feat_gemm_kernel<<<dim3(DIM / BN, (N_Q + M_KV) / BM), 256>>>(x, y, W, b);
    normalize_kernel<<<N_Q + M_KV, 256>>>();
    sim_gemm_kernel<<<dim3(M_KV / BN, N_Q / BM), 256>>>();
    topk_kernel<<<(N_Q * 32) / 256, 256>>>(out, out_size);
}